// round 1
// baseline (speedup 1.0000x reference)
#include <cuda_runtime.h>
#include <math.h>

#define BB 16
#define SEQL 1025
#define EMB 384
#define HDS 6
#define HD 64
#define NF 32
#define ROWS (BB*SEQL)

// ---------------- scratch (static device globals; no allocations) ----------
__device__ float g_q[(size_t)BB*HDS*SEQL*HD];      // [b,h,s,d]
__device__ float g_k[(size_t)BB*HDS*SEQL*HD];
__device__ float g_v[(size_t)BB*HDS*SEQL*HD];
__device__ float g_ao[(size_t)ROWS*EMB];           // [b,s,e] attn output
__device__ float g_cos[SEQL*HDS*NF];
__device__ float g_sin[SEQL*HDS*NF];
__device__ float g_freqs[HDS*NF*2];

// ---------------- XLA erfinv (f32 polynomial, Giles) ------------------------
__device__ __forceinline__ float erfinv_xla(float x) {
    float w = -log1pf(-__fmul_rn(x, x));
    float p;
    if (w < 5.0f) {
        w = w - 2.5f;
        p = 2.81022636e-08f;
        p = fmaf(p, w, 3.43273939e-07f);
        p = fmaf(p, w, -3.5233877e-06f);
        p = fmaf(p, w, -4.39150654e-06f);
        p = fmaf(p, w, 0.00021858087f);
        p = fmaf(p, w, -0.00125372503f);
        p = fmaf(p, w, -0.00417768164f);
        p = fmaf(p, w, 0.246640727f);
        p = fmaf(p, w, 1.50140941f);
    } else {
        w = sqrtf(w) - 3.0f;
        p = -0.000200214257f;
        p = fmaf(p, w, 0.000100950558f);
        p = fmaf(p, w, 0.00134934322f);
        p = fmaf(p, w, -0.00367342844f);
        p = fmaf(p, w, 0.00573950773f);
        p = fmaf(p, w, -0.0076224613f);
        p = fmaf(p, w, 0.00943887047f);
        p = fmaf(p, w, 1.00167406f);
        p = fmaf(p, w, 2.83297682f);
    }
    return p * x;
}

__global__ void init_freqs(float inv_g) {
    int n = threadIdx.x;                      // 0..191 : n = h*32 + f
    if (n >= HDS * NF) return;
    float alpha0 = powf(inv_g, 1.0f);
    float alpha1 = powf(inv_g, 2.0f);
    float fi = (float)(n + 1);
    float z0 = fmodf(__fmul_rn(fi, alpha0), 1.0f);
    float z1 = fmodf(__fmul_rn(fi, alpha1), 1.0f);
    float d0 = erfinv_xla(__fmul_rn(2.0f, z0) - 1.0f);
    float d1 = erfinv_xla(__fmul_rn(2.0f, z1) - 1.0f);
    float nrm = sqrtf(__fadd_rn(__fmul_rn(d0, d0), __fmul_rn(d1, d1)));
    d0 = __fdiv_rn(d0, nrm);
    d1 = __fdiv_rn(d1, nrm);
    int f = n % NF;
    float t = __fmul_rn((float)f, (1.0f / 31.0f));     // linspace(0,1,32)
    float omega = __fmul_rn(0.1f, powf(10000.0f, t));
    g_freqs[n * 2 + 0] = __fmul_rn(d0, omega);
    g_freqs[n * 2 + 1] = __fmul_rn(d1, omega);
}

__global__ void init_trig() {
    int idx = blockIdx.x * blockDim.x + threadIdx.x;
    if (idx >= SEQL * HDS * NF) return;
    int s = idx / (HDS * NF);
    int r = idx % (HDS * NF);
    float c0 = 0.f, c1 = 0.f;
    if (s > 0) {
        int p = s - 1;
        int xi = p % 32, yi = p / 32;
        c0 = __fmul_rn(__fdiv_rn((float)xi, 31.0f), 2.0f) - 1.0f;
        c1 = __fmul_rn(__fdiv_rn((float)yi, 31.0f), 2.0f) - 1.0f;
    }
    float f0 = g_freqs[r * 2 + 0];
    float f1 = g_freqs[r * 2 + 1];
    float th = __fadd_rn(__fmul_rn(f0, c0), __fmul_rn(f1, c1));
    g_cos[idx] = cosf(th);
    g_sin[idx] = sinf(th);
}

// ---------------- QKV projection + fused RoPE -------------------------------
// grid: (257 row-blocks, 6 heads, 3 matrices), block 256.
// 64x64 output tile, K-chunks of 32. Thread (tr,tc) owns rows 4tr+i and the
// RoPE-paired columns {2tc, 2tc+1, 2tc+32, 2tc+33}.
__global__ void __launch_bounds__(256) qkv_kernel(
    const float* __restrict__ x, const float* __restrict__ Wq,
    const float* __restrict__ Wk, const float* __restrict__ Wv)
{
    int rb = blockIdx.x, h = blockIdx.y, z = blockIdx.z;
    const float* W = (z == 0) ? Wq : ((z == 1) ? Wk : Wv);
    float* outb = (z == 0) ? g_q : ((z == 1) ? g_k : g_v);

    __shared__ float xs[64][33];
    __shared__ float ws[32][64];

    int tid = threadIdx.x;
    int tr = tid >> 4, tc = tid & 15;
    float acc[4][4] = {};
    int row0 = rb * 64;

    for (int k0 = 0; k0 < EMB; k0 += 32) {
#pragma unroll
        for (int u = 0; u < 8; u++) {
            int e = tid + 256 * u;
            int rr = e >> 5, kk = e & 31;
            int gr = row0 + rr;
            xs[rr][kk] = (gr < ROWS) ? x[(size_t)gr * EMB + k0 + kk] : 0.f;
        }
#pragma unroll
        for (int u = 0; u < 8; u++) {
            int e = tid + 256 * u;
            int kk = e >> 6, cc = e & 63;
            ws[kk][cc] = W[(size_t)(k0 + kk) * EMB + h * 64 + cc];
        }
        __syncthreads();
#pragma unroll
        for (int kk = 0; kk < 32; kk++) {
            float ra[4], rbv[4];
#pragma unroll
            for (int i = 0; i < 4; i++) ra[i] = xs[tr * 4 + i][kk];
            rbv[0] = ws[kk][2 * tc];
            rbv[1] = ws[kk][2 * tc + 1];
            rbv[2] = ws[kk][2 * tc + 32];
            rbv[3] = ws[kk][2 * tc + 33];
#pragma unroll
            for (int i = 0; i < 4; i++)
#pragma unroll
                for (int j = 0; j < 4; j++)
                    acc[i][j] = fmaf(ra[i], rbv[j], acc[i][j]);
        }
        __syncthreads();
    }

#pragma unroll
    for (int i = 0; i < 4; i++) {
        int gr = row0 + tr * 4 + i;
        if (gr >= ROWS) continue;
        int b = gr / SEQL, s = gr % SEQL;
        float* dst = outb + ((size_t)(b * HDS + h) * SEQL + s) * HD;
        if (z < 2) {
#pragma unroll
            for (int j = 0; j < 2; j++) {
                int f = 2 * tc + j;
                float cv = g_cos[(s * HDS + h) * NF + f];
                float sv = g_sin[(s * HDS + h) * NF + f];
                float lo = acc[i][j], hi = acc[i][j + 2];
                dst[f]      = lo * cv - hi * sv;
                dst[f + 32] = lo * sv + hi * cv;
            }
        } else {
            dst[2 * tc]      = acc[i][0];
            dst[2 * tc + 1]  = acc[i][1];
            dst[2 * tc + 32] = acc[i][2];
            dst[2 * tc + 33] = acc[i][3];
        }
    }
}

// ---------------- Flash attention (fp32, BM=BN=64) --------------------------
__global__ void __launch_bounds__(256) attn_kernel() {
    extern __shared__ float sm[];
    float (*Qs)[65] = (float(*)[65])sm;
    float (*Ks)[65] = (float(*)[65])(sm + 64 * 65);
    float (*Vs)[65] = (float(*)[65])(sm + 2 * 64 * 65);
    float (*Ps)[65] = (float(*)[65])(sm + 3 * 64 * 65);

    int qb = blockIdx.x;     // 0..16
    int bh = blockIdx.y;     // 0..95 (= b*6 + h)
    const float* Q = g_q + (size_t)bh * SEQL * HD;
    const float* K = g_k + (size_t)bh * SEQL * HD;
    const float* V = g_v + (size_t)bh * SEQL * HD;

    int tid = threadIdx.x, tr = tid >> 4, tc = tid & 15;

#pragma unroll
    for (int u = 0; u < 16; u++) {
        int e = tid + 256 * u;
        int rr = e >> 6, dd = e & 63;
        int s = qb * 64 + rr;
        Qs[rr][dd] = (s < SEQL) ? Q[(size_t)s * HD + dd] : 0.f;
    }

    float o[4][4] = {};
    float m[4] = {-INFINITY, -INFINITY, -INFINITY, -INFINITY};
    float l[4] = {};

    for (int t = 0; t < 17; t++) {
        __syncthreads();
#pragma unroll
        for (int u = 0; u < 16; u++) {
            int e = tid + 256 * u;
            int rr = e >> 6, dd = e & 63;
            int s = t * 64 + rr;
            bool ok = (s < SEQL);
            Ks[rr][dd] = ok ? K[(size_t)s * HD + dd] : 0.f;
            Vs[rr][dd] = ok ? V[(size_t)s * HD + dd] : 0.f;
        }
        __syncthreads();

        float sacc[4][4] = {};
#pragma unroll
        for (int dd = 0; dd < 64; dd++) {
            float ra[4], rb2[4];
#pragma unroll
            for (int i = 0; i < 4; i++) ra[i] = Qs[tr * 4 + i][dd];
#pragma unroll
            for (int j = 0; j < 4; j++) rb2[j] = Ks[tc * 4 + j][dd];
#pragma unroll
            for (int i = 0; i < 4; i++)
#pragma unroll
                for (int j = 0; j < 4; j++)
                    sacc[i][j] = fmaf(ra[i], rb2[j], sacc[i][j]);
        }

#pragma unroll
        for (int i = 0; i < 4; i++)
#pragma unroll
            for (int j = 0; j < 4; j++) {
                int col = t * 64 + tc * 4 + j;
                sacc[i][j] = (col < SEQL) ? sacc[i][j] * 0.125f : -INFINITY;
            }

#pragma unroll
        for (int i = 0; i < 4; i++) {
            float rm = fmaxf(fmaxf(sacc[i][0], sacc[i][1]),
                             fmaxf(sacc[i][2], sacc[i][3]));
#pragma unroll
            for (int off = 1; off < 16; off <<= 1)
                rm = fmaxf(rm, __shfl_xor_sync(0xffffffffu, rm, off));
            float mn = fmaxf(m[i], rm);
            float corr = __expf(m[i] - mn);
            float pv[4];
            float rs = 0.f;
#pragma unroll
            for (int j = 0; j < 4; j++) {
                pv[j] = __expf(sacc[i][j] - mn);
                rs += pv[j];
            }
#pragma unroll
            for (int off = 1; off < 16; off <<= 1)
                rs += __shfl_xor_sync(0xffffffffu, rs, off);
            l[i] = l[i] * corr + rs;
            m[i] = mn;
#pragma unroll
            for (int j = 0; j < 4; j++) {
                o[i][j] *= corr;
                Ps[tr * 4 + i][tc * 4 + j] = pv[j];
            }
        }
        __syncthreads();

#pragma unroll
        for (int kk = 0; kk < 64; kk++) {
            float ra[4], rb2[4];
#pragma unroll
            for (int i = 0; i < 4; i++) ra[i] = Ps[tr * 4 + i][kk];
#pragma unroll
            for (int j = 0; j < 4; j++) rb2[j] = Vs[kk][tc * 4 + j];
#pragma unroll
            for (int i = 0; i < 4; i++)
#pragma unroll
                for (int j = 0; j < 4; j++)
                    o[i][j] = fmaf(ra[i], rb2[j], o[i][j]);
        }
    }

    int b = bh / HDS, h = bh % HDS;
#pragma unroll
    for (int i = 0; i < 4; i++) {
        int s = qb * 64 + tr * 4 + i;
        if (s >= SEQL) continue;
        float inv = 1.0f / l[i];
        float* dst = g_ao + ((size_t)(b * SEQL + s)) * EMB + h * HD;
#pragma unroll
        for (int j = 0; j < 4; j++) dst[tc * 4 + j] = o[i][j] * inv;
    }
}

// ---------------- Output projection + bias ----------------------------------
__global__ void __launch_bounds__(256) proj_kernel(
    const float* __restrict__ Wo, const float* __restrict__ bo,
    float* __restrict__ out)
{
    int rb = blockIdx.x, cb = blockIdx.y;

    __shared__ float xs[64][33];
    __shared__ float ws[32][64];

    int tid = threadIdx.x;
    int tr = tid >> 4, tc = tid & 15;
    float acc[4][4] = {};
    int row0 = rb * 64;

    for (int k0 = 0; k0 < EMB; k0 += 32) {
#pragma unroll
        for (int u = 0; u < 8; u++) {
            int e = tid + 256 * u;
            int rr = e >> 5, kk = e & 31;
            int gr = row0 + rr;
            xs[rr][kk] = (gr < ROWS) ? g_ao[(size_t)gr * EMB + k0 + kk] : 0.f;
        }
#pragma unroll
        for (int u = 0; u < 8; u++) {
            int e = tid + 256 * u;
            int kk = e >> 6, cc = e & 63;
            ws[kk][cc] = Wo[(size_t)(k0 + kk) * EMB + cb * 64 + cc];
        }
        __syncthreads();
#pragma unroll
        for (int kk = 0; kk < 32; kk++) {
            float ra[4], rbv[4];
#pragma unroll
            for (int i = 0; i < 4; i++) ra[i] = xs[tr * 4 + i][kk];
            rbv[0] = ws[kk][2 * tc];
            rbv[1] = ws[kk][2 * tc + 1];
            rbv[2] = ws[kk][2 * tc + 32];
            rbv[3] = ws[kk][2 * tc + 33];
#pragma unroll
            for (int i = 0; i < 4; i++)
#pragma unroll
                for (int j = 0; j < 4; j++)
                    acc[i][j] = fmaf(ra[i], rbv[j], acc[i][j]);
        }
        __syncthreads();
    }

    int cbase = cb * 64;
#pragma unroll
    for (int i = 0; i < 4; i++) {
        int gr = row0 + tr * 4 + i;
        if (gr >= ROWS) continue;
        float* dst = out + (size_t)gr * EMB + cbase;
        dst[2 * tc]      = acc[i][0] + bo[cbase + 2 * tc];
        dst[2 * tc + 1]  = acc[i][1] + bo[cbase + 2 * tc + 1];
        dst[2 * tc + 32] = acc[i][2] + bo[cbase + 2 * tc + 32];
        dst[2 * tc + 33] = acc[i][3] + bo[cbase + 2 * tc + 33];
    }
}

// ---------------- launch -----------------------------------------------------
extern "C" void kernel_launch(void* const* d_in, const int* in_sizes, int n_in,
                              void* d_out, int out_size)
{
    const float* x  = (const float*)d_in[0];
    const float* Wq = (const float*)d_in[1];
    const float* Wk = (const float*)d_in[2];
    const float* Wv = (const float*)d_in[3];
    const float* Wo = (const float*)d_in[4];
    const float* bo = (const float*)d_in[5];
    float* out = (float*)d_out;

    // phi(2) exactly as the Python host loop computes it (glibc pow, doubles)
    double xg = 2.0;
    for (int it = 0; it < 10; ++it) xg = pow(1.0 + xg, 1.0 / 3.0);
    float inv_g = (float)(1.0 / xg);

    const int ATTN_SMEM = 4 * 64 * 65 * (int)sizeof(float);   // 66560 B
    cudaFuncSetAttribute(attn_kernel,
                         cudaFuncAttributeMaxDynamicSharedMemorySize, ATTN_SMEM);

    init_freqs<<<1, 192>>>(inv_g);
    init_trig<<<(SEQL * HDS * NF + 255) / 256, 256>>>();

    dim3 qkv_grid((ROWS + 63) / 64, HDS, 3);
    qkv_kernel<<<qkv_grid, 256>>>(x, Wq, Wk, Wv);

    dim3 attn_grid((SEQL + 63) / 64, BB * HDS);
    attn_kernel<<<attn_grid, 256, ATTN_SMEM>>>();

    dim3 proj_grid((ROWS + 63) / 64, EMB / 64);
    proj_kernel<<<proj_grid, 256>>>(Wo, bo, out);
}